// round 14
// baseline (speedup 1.0000x reference)
#include <cuda_runtime.h>
#include <cuda_bf16.h>
#include <cstdint>

#define TLEN   1024
#define NTHR   256            // threads per block
#define QUAD   4              // timesteps per thread in scan phase
#define NPAIR  512            // timestep pairs per row
#define NWARP  (NTHR / 32)
#define GAMMA  0.98f
#define GL     (0.98f * 0.93f)
#define EPSI   0.2f
#define MAXB   4096

__device__ float g_part[3 * MAXB];      // per-block partials (overwritten every launch)
__device__ unsigned int g_ctr = 0;      // finish ticket; reset by finalizing block

__device__ __forceinline__ float warp_sum(float v) {
#pragma unroll
    for (int o = 16; o; o >>= 1) v += __shfl_xor_sync(0xffffffffu, v, o);
    return v;
}

__device__ __forceinline__ float pick6(int a, float e0, float e1, float e2,
                                       float e3, float e4, float e5) {
    return (a == 0) ? e0 : (a == 1) ? e1 : (a == 2) ? e2
         : (a == 3) ? e3 : (a == 4) ? e4 : e5;
}

// One block per batch row b. Phase 1 = wide-load streamer (2 ts per thread-step,
// 6x LDG.128 + LDG.64). Scan operands prefetched in the PROLOGUE so their DRAM
// latency hides under phase-1 streaming (R9's winning trait).
__global__ __launch_bounds__(NTHR, 6) void ppo_fused(
    const float* __restrict__ rewards,
    const float* __restrict__ values,
    const float* __restrict__ logits,
    const float* __restrict__ logits_old,
    const int*   __restrict__ dones,     // jnp.bool_ widened to int32
    const int*   __restrict__ actions,
    float* __restrict__ out, int B)
{
    const int b    = blockIdx.x;
    const int tid  = threadIdx.x;
    const int lane = tid & 31;
    const int wrp  = tid >> 5;
    const long rowbase = (long)b * TLEN;

    __shared__ float  s_ratio[TLEN];        // 4 KB
    __shared__ float  sv[NTHR];
    __shared__ float  sWa[NWARP], sWb[NWARP], sGa[NWARP], sGb[NWARP];
    __shared__ float  sWR[NWARP], sWA[NWARP];
    __shared__ float  r0[NWARP], r1[NWARP], r2[NWARP];
    __shared__ bool   s_last;

    // ---- prologue: prefetch scan operands; latency hides under phase 1 ----
    const int t0 = tid * QUAD;
    const float4 rq = *reinterpret_cast<const float4*>(rewards + rowbase + t0);
    const float4 vq = *reinterpret_cast<const float4*>(values  + rowbase + t0);
    int dmask;
    {
        const int4 dq = *reinterpret_cast<const int4*>(dones + rowbase + t0);
        dmask = (dq.x != 0) | ((dq.y != 0) << 1) | ((dq.z != 0) << 2) | ((dq.w != 0) << 3);
    }
    sv[tid] = vq.x;        // ordered by the phase-boundary barrier below

    // ============ Phase 1: wide-load streaming (no barriers) ============
    const float4* L4 = reinterpret_cast<const float4*>(logits)     + (long)b * (TLEN * 6 / 4);
    const float4* O4 = reinterpret_cast<const float4*>(logits_old) + (long)b * (TLEN * 6 / 4);
    const int2*   A2 = reinterpret_cast<const int2*>(actions)      + (long)b * NPAIR;

    float ent = 0.f;
#pragma unroll
    for (int i = 0; i < 2; i++) {
        const int p = i * NTHR + tid;                 // pair index in row, 0..511
        const float4 l0 = L4[p * 3], l1 = L4[p * 3 + 1], l2 = L4[p * 3 + 2];
        const float4 o0 = O4[p * 3], o1 = O4[p * 3 + 1], o2 = O4[p * 3 + 2];
        const int2   aa = A2[p];

        // ts 2p  : logits l0.x..l1.y   old o0.x..o1.y
        // ts 2p+1: logits l1.z..l2.w   old o1.z..o2.w
        // (no max-subtraction: logits ~ N(0,1), fp32 exp cannot overflow)
        float s0 = __expf(l0.x) + __expf(l0.y) + __expf(l0.z)
                 + __expf(l0.w) + __expf(l1.x) + __expf(l1.y);
        float q0 = __expf(o0.x) + __expf(o0.y) + __expf(o0.z)
                 + __expf(o0.w) + __expf(o1.x) + __expf(o1.y);
        const float xa0 = pick6(aa.x, l0.x, l0.y, l0.z, l0.w, l1.x, l1.y);
        const float ya0 = pick6(aa.x, o0.x, o0.y, o0.z, o0.w, o1.x, o1.y);
        const float lp0 = xa0 - __logf(s0);
        // ratio = exp(lp - lpo) = exp(lp - ya) * sum_old
        const float rv0 = __expf(lp0 - ya0) * q0;

        float s1 = __expf(l1.z) + __expf(l1.w) + __expf(l2.x)
                 + __expf(l2.y) + __expf(l2.z) + __expf(l2.w);
        float q1 = __expf(o1.z) + __expf(o1.w) + __expf(o2.x)
                 + __expf(o2.y) + __expf(o2.z) + __expf(o2.w);
        const float xa1 = pick6(aa.y, l1.z, l1.w, l2.x, l2.y, l2.z, l2.w);
        const float ya1 = pick6(aa.y, o1.z, o1.w, o2.x, o2.y, o2.z, o2.w);
        const float lp1 = xa1 - __logf(s1);
        const float rv1 = __expf(lp1 - ya1) * q1;

        ent += lp0 + lp1;
        reinterpret_cast<float2*>(s_ratio)[p] = make_float2(rv0, rv1);
    }

    // ================= Phase 2: dual affine suffix scan =================
    __syncthreads();                                    // orders s_ratio + sv
    const float vnext3 = (tid < NTHR - 1) ? sv[tid + 1] : 0.f;   // v[t0+4]

    const float rr[QUAD] = {rq.x, rq.y, rq.z, rq.w};
    const float vv[QUAD] = {vq.x, vq.y, vq.z, vq.w};

    // affine pair generator: x_t = bX + aX * x_{t+1}; recomputed (not cached)
    auto affine = [&](int j, float& aRj, float& bRj, float& aAj, float& bAj) {
        const bool dn = (dmask >> j) & 1;
        if (t0 + j == TLEN - 1) {                 // terminal timestep
            aRj = 0.f; bRj = dn ? rr[j] : vv[j];
            aAj = 0.f; bAj = 0.f;
        } else {
            const float vn = (j < 3) ? vv[j + 1] : vnext3;
            aRj = dn ? 0.f : GAMMA;  bRj = rr[j];
            aAj = dn ? 0.f : GL;
            bAj = rr[j] + GAMMA * (dn ? 0.f : vn) - vv[j];   // td error
        }
    };

    // serial composition of the quad (maps x[t0+4] -> x[t0])
    float Ar, Br, Aa, Ba;
    affine(3, Ar, Br, Aa, Ba);
#pragma unroll
    for (int j = 2; j >= 0; j--) {
        float aj, bj, cj, dj;
        affine(j, aj, bj, cj, dj);
        Br = fmaf(aj, Br, bj);  Ar = aj * Ar;
        Ba = fmaf(cj, Ba, dj);  Aa = cj * Aa;
    }

    // warp-level Kogge-Stone inclusive suffix scan (both recurrences fused)
#pragma unroll
    for (int d2 = 1; d2 < 32; d2 <<= 1) {
        float Ar2 = __shfl_down_sync(0xffffffffu, Ar, d2);
        float Br2 = __shfl_down_sync(0xffffffffu, Br, d2);
        float Aa2 = __shfl_down_sync(0xffffffffu, Aa, d2);
        float Ba2 = __shfl_down_sync(0xffffffffu, Ba, d2);
        if (lane + d2 < 32) {
            Br = fmaf(Ar, Br2, Br);  Ar *= Ar2;
            Ba = fmaf(Aa, Ba2, Ba);  Aa *= Aa2;
        }
    }

    // in-warp exclusive (composition over threads [tid+1 .. warp end])
    float eAr = __shfl_down_sync(0xffffffffu, Ar, 1);
    float eBr = __shfl_down_sync(0xffffffffu, Br, 1);
    float eAa = __shfl_down_sync(0xffffffffu, Aa, 1);
    float eBa = __shfl_down_sync(0xffffffffu, Ba, 1);
    if (lane == 31) { eAr = 1.f; eBr = 0.f; eAa = 1.f; eBa = 0.f; }

    // cross-warp: exclusive suffix over the 8 warp aggregates
    if (lane == 0) { sWa[wrp] = Ar; sWb[wrp] = Br; sGa[wrp] = Aa; sGb[wrp] = Ba; }
    __syncthreads();

    if (wrp == 0 && lane < NWARP) {
        float ga = sWa[lane], gb = sWb[lane], ha = sGa[lane], hb = sGb[lane];
#pragma unroll
        for (int d2 = 1; d2 < NWARP; d2 <<= 1) {
            float ga2 = __shfl_down_sync(0xffu, ga, d2);
            float gb2 = __shfl_down_sync(0xffu, gb, d2);
            float ha2 = __shfl_down_sync(0xffu, ha, d2);
            float hb2 = __shfl_down_sync(0xffu, hb, d2);
            if (lane + d2 < NWARP) {
                gb = fmaf(ga, gb2, gb);  ga *= ga2;
                hb = fmaf(ha, hb2, hb);  ha *= ha2;
            }
        }
        float cb = __shfl_down_sync(0xffu, gb, 1);
        float db = __shfl_down_sync(0xffu, hb, 1);
        if (lane == NWARP - 1) { cb = 0.f; db = 0.f; }
        sWR[lane] = cb;                 // x_R at (w+1)*128
        sWA[lane] = db;                 // x_A at (w+1)*128
    }
    __syncthreads();

    // thread carry: x at t0+4
    float xR = fmaf(eAr, sWR[wrp], eBr);
    float xA = fmaf(eAa, sWA[wrp], eBa);

    // ================= Phase 3: losses =================
    const float4 rt4 = *reinterpret_cast<const float4*>(&s_ratio[t0]);
    const float rat[QUAD] = {rt4.x, rt4.y, rt4.z, rt4.w};

    float pt = 0.f, vt = 0.f;
#pragma unroll
    for (int j = QUAD - 1; j >= 0; j--) {
        float aj, bj, cj, dj;
        affine(j, aj, bj, cj, dj);
        xR = fmaf(aj, xR, bj);              // future return at t0+j
        xA = fmaf(cj, xA, dj);              // GAE at t0+j
        const float dv = xR - vv[j];
        vt = fmaf(dv, dv, vt);
        if (t0 + j < TLEN - 1) {
            // clip(r, 1-eps, eps) with 1-eps > eps collapses to constant eps
            pt += fminf(rat[j] * xA, EPSI * xA);
        }
    }

    // block reduction -> per-block partials
    pt = warp_sum(pt); vt = warp_sum(vt); ent = warp_sum(ent);
    if (lane == 0) { r0[wrp] = pt; r1[wrp] = vt; r2[wrp] = ent; }
    __syncthreads();

    if (tid == 0) {
        float a0 = 0.f, a1 = 0.f, a2 = 0.f;
#pragma unroll
        for (int w = 0; w < NWARP; w++) { a0 += r0[w]; a1 += r1[w]; a2 += r2[w]; }
        g_part[b]            = a0;
        g_part[MAXB + b]     = a1;
        g_part[2 * MAXB + b] = a2;
        __threadfence();
        s_last = (atomicAdd(&g_ctr, 1u) == (unsigned)(gridDim.x - 1));
    }
    __syncthreads();

    // last block to finish performs the (deterministic) final reduction
    if (s_last) {
        float s0 = 0.f, s1 = 0.f, s2 = 0.f;
        for (int i = tid; i < B; i += NTHR) {
            s0 += g_part[i];
            s1 += g_part[MAXB + i];
            s2 += g_part[2 * MAXB + i];
        }
        s0 = warp_sum(s0); s1 = warp_sum(s1); s2 = warp_sum(s2);
        if (lane == 0) { r0[wrp] = s0; r1[wrp] = s1; r2[wrp] = s2; }
        __syncthreads();
        if (tid == 0) {
            float a0 = 0.f, a1 = 0.f, a2 = 0.f;
#pragma unroll
            for (int w = 0; w < NWARP; w++) { a0 += r0[w]; a1 += r1[w]; a2 += r2[w]; }
            const double nBT  = (double)B * TLEN;
            const double nBT1 = (double)B * (TLEN - 1);
            out[0] = (float)(-(double)a0 / nBT1);   // ppo_loss
            out[1] = (float)( (double)a1 / nBT);    // value_loss
            out[2] = (float)(-(double)a2 / nBT);    // entropy_loss
            g_ctr = 0;                              // reset for next graph replay
        }
    }
}

extern "C" void kernel_launch(void* const* d_in, const int* in_sizes, int n_in,
                              void* d_out, int out_size)
{
    const float* rewards    = (const float*)d_in[0];
    const float* values     = (const float*)d_in[1];
    const float* logits     = (const float*)d_in[2];
    const float* logits_old = (const float*)d_in[3];
    const int*   dones      = (const int*)d_in[4];
    const int*   actions    = (const int*)d_in[5];
    float* out = (float*)d_out;

    const int B = in_sizes[0] / TLEN;   // 2048

    ppo_fused<<<B, NTHR>>>(rewards, values, logits, logits_old, dones, actions, out, B);
}

// round 15
// speedup vs baseline: 1.2164x; 1.2164x over previous
#include <cuda_runtime.h>
#include <cuda_bf16.h>
#include <cstdint>

#define TLEN   1024
#define NTHR   256            // threads per block
#define QUAD   4              // timesteps per thread in scan phase
#define NPAIR  512            // timestep pairs per row
#define NWARP  (NTHR / 32)
#define GAMMA  0.98f
#define GL     (0.98f * 0.93f)
#define EPSI   0.2f
#define MAXB   4096

__device__ float g_part[3 * MAXB];      // per-block partials (overwritten every launch)
__device__ unsigned int g_ctr = 0;      // finish ticket; reset by finalizing block

__device__ __forceinline__ float warp_sum(float v) {
#pragma unroll
    for (int o = 16; o; o >>= 1) v += __shfl_xor_sync(0xffffffffu, v, o);
    return v;
}

__device__ __forceinline__ float pick6(int a, float e0, float e1, float e2,
                                       float e3, float e4, float e5) {
    return (a == 0) ? e0 : (a == 1) ? e1 : (a == 2) ? e2
         : (a == 3) ? e3 : (a == 4) ? e4 : e5;
}

// One block per batch row b. Phase 1 = wide-load streamer (FIRST instructions
// are the logits LDGs — R14 showed prologue loads ahead of them regress).
// Logits are read-once -> __ldcs evict-first. Cross-warp scan is computed
// redundantly by every warp (one barrier fewer).
__global__ __launch_bounds__(NTHR, 6) void ppo_fused(
    const float* __restrict__ rewards,
    const float* __restrict__ values,
    const float* __restrict__ logits,
    const float* __restrict__ logits_old,
    const int*   __restrict__ dones,     // jnp.bool_ widened to int32
    const int*   __restrict__ actions,
    float* __restrict__ out, int B)
{
    const int b    = blockIdx.x;
    const int tid  = threadIdx.x;
    const int lane = tid & 31;
    const int wrp  = tid >> 5;
    const long rowbase = (long)b * TLEN;

    __shared__ float  s_ratio[TLEN];        // 4 KB
    __shared__ float  sv[NTHR];
    __shared__ float  sWa[NWARP], sWb[NWARP], sGa[NWARP], sGb[NWARP];
    __shared__ float  r0[NWARP], r1[NWARP], r2[NWARP];
    __shared__ bool   s_last;

    // ============ Phase 1: wide-load streaming (no barriers) ============
    const float4* L4 = reinterpret_cast<const float4*>(logits)     + (long)b * (TLEN * 6 / 4);
    const float4* O4 = reinterpret_cast<const float4*>(logits_old) + (long)b * (TLEN * 6 / 4);
    const int2*   A2 = reinterpret_cast<const int2*>(actions)      + (long)b * NPAIR;

    float ent = 0.f;
#pragma unroll
    for (int i = 0; i < 2; i++) {
        const int p = i * NTHR + tid;                 // pair index in row, 0..511
        const float4 l0 = __ldcs(L4 + p * 3), l1 = __ldcs(L4 + p * 3 + 1),
                     l2 = __ldcs(L4 + p * 3 + 2);
        const float4 o0 = __ldcs(O4 + p * 3), o1 = __ldcs(O4 + p * 3 + 1),
                     o2 = __ldcs(O4 + p * 3 + 2);
        const int2   aa = A2[p];

        // ts 2p  : logits l0.x..l1.y   old o0.x..o1.y
        // ts 2p+1: logits l1.z..l2.w   old o1.z..o2.w
        // (no max-subtraction: logits ~ N(0,1), fp32 exp cannot overflow)
        float s0 = __expf(l0.x) + __expf(l0.y) + __expf(l0.z)
                 + __expf(l0.w) + __expf(l1.x) + __expf(l1.y);
        float q0 = __expf(o0.x) + __expf(o0.y) + __expf(o0.z)
                 + __expf(o0.w) + __expf(o1.x) + __expf(o1.y);
        const float xa0 = pick6(aa.x, l0.x, l0.y, l0.z, l0.w, l1.x, l1.y);
        const float ya0 = pick6(aa.x, o0.x, o0.y, o0.z, o0.w, o1.x, o1.y);
        const float lp0 = xa0 - __logf(s0);
        // ratio = exp(lp - lpo) = exp(lp - ya) * sum_old
        const float rv0 = __expf(lp0 - ya0) * q0;

        float s1 = __expf(l1.z) + __expf(l1.w) + __expf(l2.x)
                 + __expf(l2.y) + __expf(l2.z) + __expf(l2.w);
        float q1 = __expf(o1.z) + __expf(o1.w) + __expf(o2.x)
                 + __expf(o2.y) + __expf(o2.z) + __expf(o2.w);
        const float xa1 = pick6(aa.y, l1.z, l1.w, l2.x, l2.y, l2.z, l2.w);
        const float ya1 = pick6(aa.y, o1.z, o1.w, o2.x, o2.y, o2.z, o2.w);
        const float lp1 = xa1 - __logf(s1);
        const float rv1 = __expf(lp1 - ya1) * q1;

        ent += lp0 + lp1;
        reinterpret_cast<float2*>(s_ratio)[p] = make_float2(rv0, rv1);
    }

    // ---- phase-2/3 operands (AFTER streaming loads; R13 ordering) ----
    const int t0 = tid * QUAD;
    const float4 rq = *reinterpret_cast<const float4*>(rewards + rowbase + t0);
    const float4 vq = *reinterpret_cast<const float4*>(values  + rowbase + t0);
    int dmask;
    {
        const int4 dq = *reinterpret_cast<const int4*>(dones + rowbase + t0);
        dmask = (dq.x != 0) | ((dq.y != 0) << 1) | ((dq.z != 0) << 2) | ((dq.w != 0) << 3);
    }

    // ================= Phase 2: dual affine suffix scan =================
    sv[tid] = vq.x;
    __syncthreads();                                    // orders s_ratio + sv
    const float vnext3 = (tid < NTHR - 1) ? sv[tid + 1] : 0.f;   // v[t0+4]

    const float rr[QUAD] = {rq.x, rq.y, rq.z, rq.w};
    const float vv[QUAD] = {vq.x, vq.y, vq.z, vq.w};

    // affine pair generator: x_t = bX + aX * x_{t+1}; recomputed (not cached)
    auto affine = [&](int j, float& aRj, float& bRj, float& aAj, float& bAj) {
        const bool dn = (dmask >> j) & 1;
        if (t0 + j == TLEN - 1) {                 // terminal timestep
            aRj = 0.f; bRj = dn ? rr[j] : vv[j];
            aAj = 0.f; bAj = 0.f;
        } else {
            const float vn = (j < 3) ? vv[j + 1] : vnext3;
            aRj = dn ? 0.f : GAMMA;  bRj = rr[j];
            aAj = dn ? 0.f : GL;
            bAj = rr[j] + GAMMA * (dn ? 0.f : vn) - vv[j];   // td error
        }
    };

    // serial composition of the quad (maps x[t0+4] -> x[t0])
    float Ar, Br, Aa, Ba;
    affine(3, Ar, Br, Aa, Ba);
#pragma unroll
    for (int j = 2; j >= 0; j--) {
        float aj, bj, cj, dj;
        affine(j, aj, bj, cj, dj);
        Br = fmaf(aj, Br, bj);  Ar = aj * Ar;
        Ba = fmaf(cj, Ba, dj);  Aa = cj * Aa;
    }

    // warp-level Kogge-Stone inclusive suffix scan (both recurrences fused)
#pragma unroll
    for (int d2 = 1; d2 < 32; d2 <<= 1) {
        float Ar2 = __shfl_down_sync(0xffffffffu, Ar, d2);
        float Br2 = __shfl_down_sync(0xffffffffu, Br, d2);
        float Aa2 = __shfl_down_sync(0xffffffffu, Aa, d2);
        float Ba2 = __shfl_down_sync(0xffffffffu, Ba, d2);
        if (lane + d2 < 32) {
            Br = fmaf(Ar, Br2, Br);  Ar *= Ar2;
            Ba = fmaf(Aa, Ba2, Ba);  Aa *= Aa2;
        }
    }

    // in-warp exclusive (composition over threads [tid+1 .. warp end])
    float eAr = __shfl_down_sync(0xffffffffu, Ar, 1);
    float eBr = __shfl_down_sync(0xffffffffu, Br, 1);
    float eAa = __shfl_down_sync(0xffffffffu, Aa, 1);
    float eBa = __shfl_down_sync(0xffffffffu, Ba, 1);
    if (lane == 31) { eAr = 1.f; eBr = 0.f; eAa = 1.f; eBa = 0.f; }

    // publish warp aggregates; every warp then scans them redundantly
    if (lane == 0) { sWa[wrp] = Ar; sWb[wrp] = Br; sGa[wrp] = Aa; sGb[wrp] = Ba; }
    __syncthreads();

    // redundant cross-warp exclusive suffix scan (in-register, no 3rd barrier)
    float ga = 1.f, gb = 0.f, ha = 1.f, hb = 0.f;
    if (lane < NWARP) { ga = sWa[lane]; gb = sWb[lane]; ha = sGa[lane]; hb = sGb[lane]; }
#pragma unroll
    for (int d2 = 1; d2 < NWARP; d2 <<= 1) {
        float ga2 = __shfl_down_sync(0xffffffffu, ga, d2);
        float gb2 = __shfl_down_sync(0xffffffffu, gb, d2);
        float ha2 = __shfl_down_sync(0xffffffffu, ha, d2);
        float hb2 = __shfl_down_sync(0xffffffffu, hb, d2);
        if (lane + d2 < NWARP) {
            gb = fmaf(ga, gb2, gb);  ga *= ga2;
            hb = fmaf(ha, hb2, hb);  ha *= ha2;
        }
    }
    float cb = __shfl_down_sync(0xffffffffu, gb, 1);
    float db = __shfl_down_sync(0xffffffffu, hb, 1);
    if (lane == NWARP - 1) { cb = 0.f; db = 0.f; }
    const float CR = __shfl_sync(0xffffffffu, cb, wrp);   // x_R at (wrp+1)*128
    const float CA = __shfl_sync(0xffffffffu, db, wrp);   // x_A at (wrp+1)*128

    // thread carry: x at t0+4
    float xR = fmaf(eAr, CR, eBr);
    float xA = fmaf(eAa, CA, eBa);

    // ================= Phase 3: losses =================
    const float4 rt4 = *reinterpret_cast<const float4*>(&s_ratio[t0]);
    const float rat[QUAD] = {rt4.x, rt4.y, rt4.z, rt4.w};

    float pt = 0.f, vt = 0.f;
#pragma unroll
    for (int j = QUAD - 1; j >= 0; j--) {
        float aj, bj, cj, dj;
        affine(j, aj, bj, cj, dj);
        xR = fmaf(aj, xR, bj);              // future return at t0+j
        xA = fmaf(cj, xA, dj);              // GAE at t0+j
        const float dv = xR - vv[j];
        vt = fmaf(dv, dv, vt);
        if (t0 + j < TLEN - 1) {
            // clip(r, 1-eps, eps) with 1-eps > eps collapses to constant eps
            pt += fminf(rat[j] * xA, EPSI * xA);
        }
    }

    // block reduction -> per-block partials
    pt = warp_sum(pt); vt = warp_sum(vt); ent = warp_sum(ent);
    if (lane == 0) { r0[wrp] = pt; r1[wrp] = vt; r2[wrp] = ent; }
    __syncthreads();

    if (tid == 0) {
        float a0 = 0.f, a1 = 0.f, a2 = 0.f;
#pragma unroll
        for (int w = 0; w < NWARP; w++) { a0 += r0[w]; a1 += r1[w]; a2 += r2[w]; }
        g_part[b]            = a0;
        g_part[MAXB + b]     = a1;
        g_part[2 * MAXB + b] = a2;
        __threadfence();
        s_last = (atomicAdd(&g_ctr, 1u) == (unsigned)(gridDim.x - 1));
    }
    __syncthreads();

    // last block to finish performs the (deterministic) final reduction
    if (s_last) {
        float s0 = 0.f, s1 = 0.f, s2 = 0.f;
        for (int i = tid; i < B; i += NTHR) {
            s0 += g_part[i];
            s1 += g_part[MAXB + i];
            s2 += g_part[2 * MAXB + i];
        }
        s0 = warp_sum(s0); s1 = warp_sum(s1); s2 = warp_sum(s2);
        if (lane == 0) { r0[wrp] = s0; r1[wrp] = s1; r2[wrp] = s2; }
        __syncthreads();
        if (tid == 0) {
            float a0 = 0.f, a1 = 0.f, a2 = 0.f;
#pragma unroll
            for (int w = 0; w < NWARP; w++) { a0 += r0[w]; a1 += r1[w]; a2 += r2[w]; }
            const double nBT  = (double)B * TLEN;
            const double nBT1 = (double)B * (TLEN - 1);
            out[0] = (float)(-(double)a0 / nBT1);   // ppo_loss
            out[1] = (float)( (double)a1 / nBT);    // value_loss
            out[2] = (float)(-(double)a2 / nBT);    // entropy_loss
            g_ctr = 0;                              // reset for next graph replay
        }
    }
}

extern "C" void kernel_launch(void* const* d_in, const int* in_sizes, int n_in,
                              void* d_out, int out_size)
{
    const float* rewards    = (const float*)d_in[0];
    const float* values     = (const float*)d_in[1];
    const float* logits     = (const float*)d_in[2];
    const float* logits_old = (const float*)d_in[3];
    const int*   dones      = (const int*)d_in[4];
    const int*   actions    = (const int*)d_in[5];
    float* out = (float*)d_out;

    const int B = in_sizes[0] / TLEN;   // 2048

    ppo_fused<<<B, NTHR>>>(rewards, values, logits, logits_old, dones, actions, out, B);
}